// round 4
// baseline (speedup 1.0000x reference)
#include <cuda_runtime.h>

// Parametric LIF forward — R4: phase-separated memory bursts.
// Process T in chunks of 8: burst-load 8x LDG.128, compute recurrence
// in-place in the register buffer, burst-store 8x STG.128. Goal: coarsen
// DRAM read/write interleave granularity (fewer bus turnarounds).
//
// x: [B=64, T=64, N=8192] fp32. Per channel (b,n), sequential over t:
//   u    = last * sig + x[t]
//   s    = (u >= th) ? 1 : 0
//   last = s ? 0 : u + lamb*(u - last)
//   out[t] = s

#ifndef LIF_B
#define LIF_B 64
#define LIF_T 64
#define LIF_N 8192
#endif

#define CHUNK 8   // timesteps per load/store burst

__global__ __launch_bounds__(128) void lif_fwd_kernel(
    const float* __restrict__ x,
    const float* __restrict__ tau_p,
    const float* __restrict__ lamb_p,
    const float* __restrict__ th_p,
    float* __restrict__ out)
{
    constexpr int NV = LIF_N / 4;              // 2048 float4 groups per row
    const int idx = blockIdx.x * blockDim.x + threadIdx.x;
    const int b  = idx >> 11;                  // idx / 2048
    const int nv = idx & (NV - 1);             // idx % 2048

    const float tp   = tau_p[0];
    const float sig  = 1.0f / (1.0f + __expf(-tp));
    const float lamb = lamb_p[0];
    const float th   = th_p[0];

    const float4* __restrict__ xp = reinterpret_cast<const float4*>(x)
                                    + (size_t)b * LIF_T * NV + nv;
    float4* __restrict__ op = reinterpret_cast<float4*>(out)
                              + (size_t)b * LIF_T * NV + nv;

    float l0 = 0.f, l1 = 0.f, l2 = 0.f, l3 = 0.f;

    float4 buf[CHUNK];

    #pragma unroll
    for (int c = 0; c < LIF_T / CHUNK; ++c) {
        const size_t base = (size_t)c * CHUNK * NV;

        // ---- read burst: 8 independent LDG.128 ----
        #pragma unroll
        for (int i = 0; i < CHUNK; ++i)
            buf[i] = xp[base + (size_t)i * NV];

        // ---- compute: serial recurrence, overwrite buf with spikes ----
        #pragma unroll
        for (int i = 0; i < CHUNK; ++i) {
            const float4 xv = buf[i];

            float u0 = fmaf(l0, sig, xv.x);
            float s0 = (u0 >= th) ? 1.0f : 0.0f;
            l0 = (u0 >= th) ? 0.0f : fmaf(lamb, u0 - l0, u0);

            float u1 = fmaf(l1, sig, xv.y);
            float s1 = (u1 >= th) ? 1.0f : 0.0f;
            l1 = (u1 >= th) ? 0.0f : fmaf(lamb, u1 - l1, u1);

            float u2 = fmaf(l2, sig, xv.z);
            float s2 = (u2 >= th) ? 1.0f : 0.0f;
            l2 = (u2 >= th) ? 0.0f : fmaf(lamb, u2 - l2, u2);

            float u3 = fmaf(l3, sig, xv.w);
            float s3 = (u3 >= th) ? 1.0f : 0.0f;
            l3 = (u3 >= th) ? 0.0f : fmaf(lamb, u3 - l3, u3);

            float4 sv; sv.x = s0; sv.y = s1; sv.z = s2; sv.w = s3;
            buf[i] = sv;
        }

        // ---- write burst: 8 back-to-back STG.128 ----
        #pragma unroll
        for (int i = 0; i < CHUNK; ++i)
            op[base + (size_t)i * NV] = buf[i];
    }
}

extern "C" void kernel_launch(void* const* d_in, const int* in_sizes, int n_in,
                              void* d_out, int out_size)
{
    const float* x    = (const float*)d_in[0];
    const float* tau  = (const float*)d_in[1];
    const float* lamb = (const float*)d_in[2];
    const float* th   = (const float*)d_in[3];
    float* out = (float*)d_out;

    constexpr int NV = LIF_N / 4;
    constexpr int total = LIF_B * NV;          // 131072 threads
    constexpr int block = 128;
    lif_fwd_kernel<<<total / block, block>>>(x, tau, lamb, th, out);
}